// round 1
// baseline (speedup 1.0000x reference)
#include <cuda_runtime.h>

// Problem constants (fixed shapes): B=8, N=4096, C=256, K=8192
#define RTOT  32768          // B*N rows
#define CDIM  256
#define KTOT  8192
#define MT    64             // rows per CTA
#define KT    64             // codes per K-tile
#define NCTA  (RTOT / MT)    // 512
#define NKT   (KTOT / KT)    // 128
#define APAD  260            // padded row stride for A (floats) — keeps LDS conflict-free
#define ASIZE (MT * APAD)    // 16640 floats
#define ABYTES (ASIZE * 4)   // 66560
#define BSLOTS (KT * 8)      // 512 float4 slots (64 codes x 8 float4 of C-chunk)
#define BBYTES (BSLOTS * 16) // 8192
#define SMEM_BYTES (ABYTES + BBYTES)

#define CODES_ELEMS 8388608        // 8*4096*256
#define IDX_OFF     8388608
#define DIST_OFF    (8388608 + 32768)

__device__ float g_cbsq[KTOT];
__device__ float g_xsq[RTOT];
__device__ int   g_idx[RTOT];

// ---------------------------------------------------------------------------
// Row sum-of-squares: one warp per row (256 floats = 2 x float4 per lane)
// which==0 -> g_xsq, which==1 -> g_cbsq
// ---------------------------------------------------------------------------
__global__ void rowsq_kernel(const float* __restrict__ in, int rows, int which) {
    int gw   = (blockIdx.x * blockDim.x + threadIdx.x) >> 5;
    int lane = threadIdx.x & 31;
    if (gw >= rows) return;
    const float4* p = reinterpret_cast<const float4*>(in) + gw * (CDIM / 4);
    float s = 0.f;
#pragma unroll
    for (int k = 0; k < 2; ++k) {
        float4 v = p[lane + 32 * k];
        s += v.x * v.x + v.y * v.y + v.z * v.z + v.w * v.w;
    }
#pragma unroll
    for (int o = 16; o; o >>= 1) s += __shfl_xor_sync(0xffffffffu, s, o);
    if (lane == 0) {
        if (which == 0) g_xsq[gw] = s;
        else            g_cbsq[gw] = s;
    }
}

// Packed f32x2 FMA — ptxas emits FFMA2 only from this PTX form.
__device__ __forceinline__ void ffma2(unsigned long long& d,
                                      unsigned long long a,
                                      unsigned long long b) {
    asm("fma.rn.f32x2 %0, %1, %2, %0;" : "+l"(d) : "l"(a), "l"(b));
}

// ---------------------------------------------------------------------------
// Main kernel: per CTA, 64 rows vs all 8192 codes.
//  A (queries) resident in smem [64][260].
//  B (codes) streamed in 64-code x 32-C chunks, register-staged double buffer,
//  stored C-major as float4 slots with XOR swizzle slot = code*8 + (cv ^ (code>>2 & 7)).
//  Thread (tx,ty): tx=tid&15 owns codes tx*4..tx*4+3 of tile; ty=tid>>4 owns rows ty*4..+3.
//  Accumulators packed f32x2 along C (even/odd partial sums), folded at epilogue.
// ---------------------------------------------------------------------------
__global__ __launch_bounds__(256)
void vq_main_kernel(const float* __restrict__ x,
                    const float* __restrict__ cb,
                    float* __restrict__ out) {
    extern __shared__ float smem[];
    float*  As = smem;
    float4* B4 = reinterpret_cast<float4*>(smem + ASIZE);

    int tid = threadIdx.x;
    int tx  = tid & 15;
    int ty  = tid >> 4;
    int rowBase = blockIdx.x * MT;

    // ---- Fill resident A tile (coalesced float4 both sides) ----
    const float4* x4 = reinterpret_cast<const float4*>(x + (size_t)rowBase * CDIM);
#pragma unroll
    for (int it = 0; it < 16; ++it) {
        int e = tid + it * 256;          // 0..4095
        int r = e >> 6, cv = e & 63;
        float4 v = x4[e];
        *reinterpret_cast<float4*>(&As[r * APAD + cv * 4]) = v;
    }

    const float4* cb4 = reinterpret_cast<const float4*>(cb);
    float4 breg0, breg1;
    {   // preload (kt=0, ck=0)
        int e0 = tid, e1 = tid + 256;
        breg0 = cb4[(e0 >> 3) * 64 + (e0 & 7)];
        breg1 = cb4[(e1 >> 3) * 64 + (e1 & 7)];
    }

    float minv[4] = {3.4e38f, 3.4e38f, 3.4e38f, 3.4e38f};
    int   mini[4] = {0, 0, 0, 0};

#pragma unroll 1
    for (int kt = 0; kt < NKT; ++kt) {
        // prefetch |c|^2 for this thread's 4 codes (consumed in epilogue)
        float cbr[4];
#pragma unroll
        for (int j = 0; j < 4; ++j) cbr[j] = __ldg(&g_cbsq[kt * KT + tx * 4 + j]);

        unsigned long long acc[4][4];
#pragma unroll
        for (int i = 0; i < 4; ++i)
#pragma unroll
            for (int j = 0; j < 4; ++j) acc[i][j] = 0ull;

#pragma unroll 1
        for (int ck = 0; ck < 8; ++ck) {
            __syncthreads();   // guard B store vs previous chunk's reads
            {   // store staged registers -> swizzled smem
                int e0 = tid, e1 = tid + 256;
                int c0 = e0 >> 3, w0 = e0 & 7;
                int c1 = e1 >> 3, w1 = e1 & 7;
                B4[c0 * 8 + (w0 ^ ((c0 >> 2) & 7))] = breg0;
                B4[c1 * 8 + (w1 ^ ((c1 >> 2) & 7))] = breg1;
            }
            __syncthreads();
            {   // issue next chunk's global loads (latency hidden behind compute)
                int kt2 = kt, ck2 = ck + 1;
                if (ck2 == 8) { ck2 = 0; kt2 = (kt + 1 < NKT) ? kt + 1 : kt; }
                int e0 = tid, e1 = tid + 256;
                breg0 = cb4[((size_t)kt2 * 64 + (e0 >> 3)) * 64 + ck2 * 8 + (e0 & 7)];
                breg1 = cb4[((size_t)kt2 * 64 + (e1 >> 3)) * 64 + ck2 * 8 + (e1 & 7)];
            }

            // ---- compute this 32-C chunk ----
            const float* Abase = &As[(ty * 4) * APAD + ck * 32];
#pragma unroll
            for (int q = 0; q < 32; q += 4) {
                ulonglong2 av[4];
#pragma unroll
                for (int i = 0; i < 4; ++i)
                    av[i] = *reinterpret_cast<const ulonglong2*>(Abase + i * APAD + q);
#pragma unroll
                for (int j = 0; j < 4; ++j) {
                    int code = tx * 4 + j;
                    ulonglong2 bv = *reinterpret_cast<const ulonglong2*>(
                        &B4[code * 8 + ((q >> 2) ^ (tx & 7))]);
#pragma unroll
                    for (int i = 0; i < 4; ++i) {
                        ffma2(acc[i][j], av[i].x, bv.x);
                        ffma2(acc[i][j], av[i].y, bv.y);
                    }
                }
            }
        }

        // ---- epilogue: val = |c|^2 - 2*dot ; running argmin (tile-ascending order) ----
#pragma unroll
        for (int j = 0; j < 4; ++j) {
            int codeg = kt * KT + tx * 4 + j;
#pragma unroll
            for (int i = 0; i < 4; ++i) {
                float lo, hi;
                asm("mov.b64 {%0,%1}, %2;" : "=f"(lo), "=f"(hi) : "l"(acc[i][j]));
                float val = fmaf(-2.f, lo + hi, cbr[j]);
                if (val < minv[i]) { minv[i] = val; mini[i] = codeg; }
            }
        }
    }

    // ---- cross-thread (tx) reduction per row; reuse B smem ----
    __syncthreads();
    float* redv = smem + ASIZE;                                    // 64*16 floats
    int*   redi = reinterpret_cast<int*>(smem + ASIZE + MT * 16);  // 64*16 ints
#pragma unroll
    for (int i = 0; i < 4; ++i) {
        redv[(ty * 4 + i) * 16 + tx] = minv[i];
        redi[(ty * 4 + i) * 16 + tx] = mini[i];
    }
    __syncthreads();
    if (tid < MT) {
        float bv = 3.4e38f;
        int   bi = 0x7fffffff;
#pragma unroll
        for (int t = 0; t < 16; ++t) {
            float v  = redv[tid * 16 + t];
            int   ii = redi[tid * 16 + t];
            if (v < bv || (v == bv && ii < bi)) { bv = v; bi = ii; }
        }
        int gr = rowBase + tid;
        out[IDX_OFF  + gr] = (float)bi;            // idx (numeric, exact < 2^24)
        out[DIST_OFF + gr] = g_xsq[gr] + bv;       // min squared L2
        g_idx[gr] = bi;
    }
}

// ---------------------------------------------------------------------------
// Gather codes: out[row, :] = cb[idx[row], :]
// ---------------------------------------------------------------------------
__global__ void gather_kernel(const float* __restrict__ cb, float* __restrict__ out) {
    int row = blockIdx.x;
    int idx = g_idx[row];
    const float4* src = reinterpret_cast<const float4*>(cb + (size_t)idx * CDIM);
    float4*       dst = reinterpret_cast<float4*>(out + (size_t)row * CDIM);
    dst[threadIdx.x] = src[threadIdx.x];           // blockDim = 64
}

extern "C" void kernel_launch(void* const* d_in, const int* in_sizes, int n_in,
                              void* d_out, int out_size) {
    const float* x  = (const float*)d_in[0];   // z_e_x  [8,4096,256] f32
    const float* cb = (const float*)d_in[1];   // codebook [8192,256] f32
    float* out = (float*)d_out;                // codes | idx | distances (f32)

    cudaFuncSetAttribute(vq_main_kernel,
                         cudaFuncAttributeMaxDynamicSharedMemorySize, SMEM_BYTES);

    rowsq_kernel<<<(RTOT * 32) / 256, 256>>>(x, RTOT, 0);
    rowsq_kernel<<<(KTOT * 32) / 256, 256>>>(cb, KTOT, 1);
    vq_main_kernel<<<NCTA, 256, SMEM_BYTES>>>(x, cb, out);
    gather_kernel<<<RTOT, 64>>>(cb, out);
}

// round 4
// speedup vs baseline: 2.1411x; 2.1411x over previous
#include <cuda_runtime.h>
#include <cuda_fp16.h>
#include <cstdint>

// ===== problem constants =====
#define RTOT  32768
#define CDIM  256
#define KTOT  8192
#define MT    128
#define NT    128
#define KSTEPS 48              // 3 products: hi*hi (0-15), lo*hi (16-31), hi*lo (32-47)
#define NUM_MT (RTOT/MT)       // 256
#define NUM_NT (KTOT/NT)       // 64
#define JOBS  (NUM_MT*NUM_NT)  // 16384
#define NCTA  148
#define THREADS 256

#define SMEM_A    0
#define SMEM_B    131072
#define SMEM_CBSQ 147456
#define SMEM_TOTAL 180224

#define IDX_OFF  8388608
#define DIST_OFF (8388608+32768)

#define MARGIN 2e-3f

// ===== device globals (static scratch) =====
__device__ uint4 g_Aimg[(size_t)NUM_MT*8192];   // [mtile][panel(32)][256 units] swizzled, [hi|lo]
__device__ uint4 g_Bimg[(size_t)NUM_NT*8192];   // [ntile][panel(32)][256 units] swizzled, [hi|lo]
__device__ float g_cbsq[KTOT];
__device__ float g_xsq[RTOT];
__device__ int   g_idx[RTOT];
__device__ unsigned long long g_best[RTOT];
__device__ unsigned int g_best2[RTOT];
__device__ int g_fixcnt;
__device__ int g_fixrows[RTOT];

// ===== helpers =====
__device__ __forceinline__ uint32_t smem_u32(const void* p) {
    uint32_t a;
    asm("{ .reg .u64 t; cvta.to.shared.u64 t, %1; cvt.u32.u64 %0, t; }" : "=r"(a) : "l"(p));
    return a;
}
__device__ __forceinline__ void cp_async16(uint32_t sa, const void* g) {
    asm volatile("cp.async.cg.shared.global [%0], [%1], 16;" :: "r"(sa), "l"(g));
}
#define CP_COMMIT() asm volatile("cp.async.commit_group;" ::: "memory")
#define CP_WAIT(N)  asm volatile("cp.async.wait_group %0;" :: "n"(N) : "memory")

__device__ __forceinline__ void ldsm4(uint32_t* r, uint32_t addr) {
    asm volatile("ldmatrix.sync.aligned.m8n8.x4.shared.b16 {%0,%1,%2,%3}, [%4];"
        : "=r"(r[0]), "=r"(r[1]), "=r"(r[2]), "=r"(r[3]) : "r"(addr));
}
__device__ __forceinline__ void mma16816(float* c, const uint32_t* a, uint32_t b0, uint32_t b1) {
    asm volatile("mma.sync.aligned.m16n8k16.row.col.f32.f16.f16.f32 "
        "{%0,%1,%2,%3}, {%4,%5,%6,%7}, {%8,%9}, {%0,%1,%2,%3};"
        : "+f"(c[0]), "+f"(c[1]), "+f"(c[2]), "+f"(c[3])
        : "r"(a[0]), "r"(a[1]), "r"(a[2]), "r"(a[3]), "r"(b0), "r"(b1));
}
__device__ __forceinline__ uint32_t encf(float f) {
    uint32_t u = __float_as_uint(f);
    return (u & 0x80000000u) ? ~u : (u | 0x80000000u);
}
__device__ __forceinline__ float decf(uint32_t e) {
    uint32_t u = (e & 0x80000000u) ? (e & 0x7fffffffu) : ~e;
    return __uint_as_float(u);
}
__device__ __forceinline__ uint32_t packh2(__half a, __half b) {
    __half2 h = __halves2half2(a, b);
    return *reinterpret_cast<uint32_t*>(&h);
}

// ===== small kernels =====
__global__ void init_kernel() {
    int i = blockIdx.x * 256 + threadIdx.x;
    g_best[i] = ~0ull;
    g_best2[i] = 0xFFFFFFFFu;
    if (i == 0) g_fixcnt = 0;
}

__global__ void rowsq_kernel(const float* __restrict__ in, int rows, int which) {
    int gw = (blockIdx.x * blockDim.x + threadIdx.x) >> 5;
    int lane = threadIdx.x & 31;
    if (gw >= rows) return;
    const float4* p = reinterpret_cast<const float4*>(in) + (size_t)gw * (CDIM / 4);
    float s = 0.f;
#pragma unroll
    for (int k = 0; k < 2; ++k) {
        float4 v = p[lane + 32 * k];
        s += v.x*v.x + v.y*v.y + v.z*v.z + v.w*v.w;
    }
#pragma unroll
    for (int o = 16; o; o >>= 1) s += __shfl_xor_sync(0xffffffffu, s, o);
    if (lane == 0) { if (which == 0) g_xsq[gw] = s; else g_cbsq[gw] = s; }
}

// Split fp32 row into [hi fp16 panels 0-15 | lo fp16 panels 16-31], pre-swizzled image.
__device__ __forceinline__ void prep_unit(const float* __restrict__ src, int t, uint4* img) {
    int row = t >> 6, u = t & 63;
    int ks = u >> 1, kh = u & 1;
    int kext = ks * 16 + kh * 8;
    const float* r = src + (size_t)row * CDIM;
    __half h[8];
    if (kext < 256) {
#pragma unroll
        for (int i = 0; i < 8; ++i) h[i] = __float2half(r[kext + i]);
    } else {
        int d = kext - 256;
#pragma unroll
        for (int i = 0; i < 8; ++i) {
            float v = r[d + i];
            __half h0 = __float2half(v);
            h[i] = __float2half(v - __half2float(h0));
        }
    }
    uint4 val;
    val.x = packh2(h[0], h[1]); val.y = packh2(h[2], h[3]);
    val.z = packh2(h[4], h[5]); val.w = packh2(h[6], h[7]);
    int tile = row >> 7, rl = row & 127;
    int phys = (rl * 2 + kh) ^ ((rl >> 2) & 1);
    img[(size_t)tile * 8192 + ks * 256 + phys] = val;
}

__global__ void prep_a_kernel(const float* __restrict__ x) {
    prep_unit(x, blockIdx.x * 256 + threadIdx.x, g_Aimg);
}
__global__ void prep_b_kernel(const float* __restrict__ cb) {
    prep_unit(cb, blockIdx.x * 256 + threadIdx.x, g_Bimg);
}

// ===== main HMMA kernel =====
// panel maps: A panel for kstep, B panel for kstep
__device__ __forceinline__ int PA(int ks) { return (ks < 32) ? ks : ks - 32; }
__device__ __forceinline__ int PB(int ks) { return (ks < 16) ? ks : ks - 16; }

__device__ __forceinline__ void issue_B(uint32_t smemB, int slot, int nt, int panel, int tid) {
    const uint4* src = g_Bimg + (size_t)nt * 8192 + panel * 256 + tid;
    cp_async16(smemB + slot * 4096 + tid * 16, src);
}
__device__ __forceinline__ void issue_A(uint32_t smemA, int m, int tid) {
    const uint4* src = g_Aimg + (size_t)m * 8192 + tid;
#pragma unroll
    for (int i = 0; i < 32; ++i)
        cp_async16(smemA + (tid + i * 256) * 16, src + i * 256);
}
__device__ __forceinline__ void upd(float v, int c, float& bv, int& bi, float& sv) {
    if (v < bv) { sv = bv; bv = v; bi = c; }
    else if (v < sv) sv = v;
}

__global__ __launch_bounds__(THREADS, 1)
void vq_hmma_kernel() {
    extern __shared__ char smem[];
    uint32_t sb = smem_u32(smem);
    uint32_t smA = sb + SMEM_A, smB = sb + SMEM_B;
    float* cbsq_s = reinterpret_cast<float*>(smem + SMEM_CBSQ);

    int tid = threadIdx.x;
    int l = tid & 31, w = tid >> 5;
    int wm = w >> 1, wn = w & 1;

    // per-thread ldmatrix offsets (bytes inside a 4KB panel)
    uint32_t aoff[2], boff[4];
#pragma unroll
    for (int mt = 0; mt < 2; ++mt) {
        int row = wm * 32 + mt * 16 + (l & 15);
        int kh = l >> 4;
        aoff[mt] = (uint32_t)(((row * 2 + kh) ^ ((row >> 2) & 1)) << 4);
    }
#pragma unroll
    for (int nt4 = 0; nt4 < 4; ++nt4) {
        int code = wn * 64 + nt4 * 16 + (l & 7) + ((l >> 4) << 3);
        int kh = (l >> 3) & 1;
        boff[nt4] = (uint32_t)(((code * 2 + kh) ^ ((code >> 2) & 1)) << 4);
    }

    int start = (int)(((long long)blockIdx.x * JOBS) / NCTA);
    int end   = (int)(((long long)(blockIdx.x + 1) * JOBS) / NCTA);

    // resident cbsq
    for (int i = tid; i < KTOT; i += THREADS) cbsq_s[i] = g_cbsq[i];

    int cur_m = start >> 6;
    issue_A(smA, cur_m, tid); CP_COMMIT();
    {   int nt0 = start & 63;
        issue_B(smB, 0, nt0, PB(0), tid); CP_COMMIT();
        issue_B(smB, 1, nt0, PB(1), tid); CP_COMMIT();
        issue_B(smB, 2, nt0, PB(2), tid); CP_COMMIT();
    }

    // running per-row argmin state: rows indexed [mt][half]
    float rb[2][2] = {{3.4e38f,3.4e38f},{3.4e38f,3.4e38f}};
    float rs[2][2] = {{3.4e38f,3.4e38f},{3.4e38f,3.4e38f}};
    int   ri[2][2] = {{0,0},{0,0}};

    for (int j = start; j < end; ++j) {
        int ntj = j & 63;
        int jn = j + 1;
        bool nx_same = (jn < end) && ((jn >> 6) == cur_m);
        int nx_nt = jn & 63;

        float acc[2][8][4];
#pragma unroll
        for (int mt = 0; mt < 2; ++mt)
#pragma unroll
            for (int nb = 0; nb < 8; ++nb)
#pragma unroll
                for (int q = 0; q < 4; ++q) acc[mt][nb][q] = 0.f;

#pragma unroll 4
        for (int ks = 0; ks < KSTEPS; ++ks) {
            CP_WAIT(2);
            __syncthreads();
            int s = ks + 3;
            if (s < KSTEPS) issue_B(smB, s & 3, ntj, PB(s), tid);
            else if (nx_same) issue_B(smB, s & 3, nx_nt, PB(s - KSTEPS), tid);
            CP_COMMIT();

            uint32_t Apan = smA + PA(ks) * 4096;
            uint32_t Bpan = smB + (ks & 3) * 4096;
            uint32_t af[2][4], bf[4][4];
            ldsm4(af[0], Apan + aoff[0]);
            ldsm4(af[1], Apan + aoff[1]);
#pragma unroll
            for (int nt4 = 0; nt4 < 4; ++nt4) ldsm4(bf[nt4], Bpan + boff[nt4]);
#pragma unroll
            for (int mt = 0; mt < 2; ++mt)
#pragma unroll
                for (int nt4 = 0; nt4 < 4; ++nt4) {
                    mma16816(acc[mt][nt4*2  ], af[mt], bf[nt4][0], bf[nt4][1]);
                    mma16816(acc[mt][nt4*2+1], af[mt], bf[nt4][2], bf[nt4][3]);
                }
        }
        __syncthreads();   // all warps done with ring slots / A panels

        bool m_change = (jn < end) && !nx_same;
        if (m_change) {
            issue_A(smA, jn >> 6, tid); CP_COMMIT();
            issue_B(smB, 0, nx_nt, PB(0), tid); CP_COMMIT();
            issue_B(smB, 1, nx_nt, PB(1), tid); CP_COMMIT();
            issue_B(smB, 2, nx_nt, PB(2), tid); CP_COMMIT();
        }

        // ---- epilogue: val = |c|^2 - 2*dot ; running (best, idx, second) ----
        int nbase = ntj * 128 + wn * 64;
#pragma unroll
        for (int mt = 0; mt < 2; ++mt)
#pragma unroll
            for (int nb = 0; nb < 8; ++nb) {
                int c0 = nbase + nb * 8 + (l & 3) * 2;
                float q0 = cbsq_s[c0], q1 = cbsq_s[c0 + 1];
                upd(fmaf(-2.f, acc[mt][nb][0], q0), c0,     rb[mt][0], ri[mt][0], rs[mt][0]);
                upd(fmaf(-2.f, acc[mt][nb][1], q1), c0 + 1, rb[mt][0], ri[mt][0], rs[mt][0]);
                upd(fmaf(-2.f, acc[mt][nb][2], q0), c0,     rb[mt][1], ri[mt][1], rs[mt][1]);
                upd(fmaf(-2.f, acc[mt][nb][3], q1), c0 + 1, rb[mt][1], ri[mt][1], rs[mt][1]);
            }

        if (m_change || jn == end) {
            // flush 4 rows: quad-merge then atomic dance
#pragma unroll
            for (int mt = 0; mt < 2; ++mt)
#pragma unroll
                for (int h = 0; h < 2; ++h) {
                    float bv = rb[mt][h], sv = rs[mt][h];
                    int bi = ri[mt][h];
#pragma unroll
                    for (int o = 1; o < 4; o <<= 1) {
                        float ov = __shfl_xor_sync(0xffffffffu, bv, o);
                        int   oi = __shfl_xor_sync(0xffffffffu, bi, o);
                        float os = __shfl_xor_sync(0xffffffffu, sv, o);
                        if (ov < bv || (ov == bv && oi < bi)) {
                            sv = fminf(bv, os); bv = ov; bi = oi;
                        } else {
                            sv = fminf(sv, ov);
                        }
                    }
                    if ((l & 3) == 0) {
                        int r = cur_m * MT + wm * 32 + mt * 16 + h * 8 + (l >> 2);
                        unsigned long long key =
                            ((unsigned long long)encf(bv) << 32) | (uint32_t)bi;
                        unsigned long long old = atomicMin(&g_best[r], key);
                        uint32_t oldenc = (uint32_t)(old >> 32);
                        uint32_t be = encf(bv);
                        uint32_t cand = min(encf(sv), max(be, oldenc));
                        atomicMin(&g_best2[r], cand);
                    }
                    rb[mt][h] = 3.4e38f; rs[mt][h] = 3.4e38f; ri[mt][h] = 0;
                }
            if (jn < end) cur_m = jn >> 6;
        }
    }
}

// ===== finalize: decode, flag close rows =====
__global__ void final_kernel(float* __restrict__ out) {
    int i = blockIdx.x * 256 + threadIdx.x;
    unsigned long long key = g_best[i];
    int idx = (int)(uint32_t)key;
    float val = decf((uint32_t)(key >> 32));
    float sec = decf(g_best2[i]);
    out[IDX_OFF + i]  = (float)idx;
    out[DIST_OFF + i] = g_xsq[i] + val;
    g_idx[i] = idx;
    if (sec - val < MARGIN) {
        int p = atomicAdd(&g_fixcnt, 1);
        g_fixrows[p] = i;
    }
}

// ===== exact fp32 rescan for flagged rows =====
__global__ void fixup_kernel(const float* __restrict__ x, const float* __restrict__ cb,
                             float* __restrict__ out) {
    __shared__ float xs[CDIM];
    __shared__ unsigned long long keys[256];
    int tid = threadIdx.x;
    int n = g_fixcnt;
    for (int fi = blockIdx.x; fi < n; fi += gridDim.x) {
        int row = g_fixrows[fi];
        if (tid < CDIM) xs[tid] = x[(size_t)row * CDIM + tid];
        __syncthreads();
        float bv = 3.4e38f; int bi = 0x7fffffff;
        for (int c = tid; c < KTOT; c += 256) {
            const float4* cr = reinterpret_cast<const float4*>(cb + (size_t)c * CDIM);
            float dot = 0.f;
#pragma unroll
            for (int q = 0; q < 64; ++q) {
                float4 v = cr[q];
                const float4 xv = *reinterpret_cast<const float4*>(&xs[q * 4]);
                dot = fmaf(v.x, xv.x, dot); dot = fmaf(v.y, xv.y, dot);
                dot = fmaf(v.z, xv.z, dot); dot = fmaf(v.w, xv.w, dot);
            }
            float val = fmaf(-2.f, dot, g_cbsq[c]);
            if (val < bv) { bv = val; bi = c; }
        }
        keys[tid] = ((unsigned long long)encf(bv) << 32) | (uint32_t)bi;
        __syncthreads();
        if (tid == 0) {
            unsigned long long best = keys[0];
            for (int t = 1; t < 256; ++t) if (keys[t] < best) best = keys[t];
            int idx = (int)(uint32_t)best;
            out[IDX_OFF + row]  = (float)idx;
            out[DIST_OFF + row] = g_xsq[row] + decf((uint32_t)(best >> 32));
            g_idx[row] = idx;
        }
        __syncthreads();
    }
}

// ===== gather codes =====
__global__ void gather_kernel(const float* __restrict__ cb, float* __restrict__ out) {
    int tid = threadIdx.x;
    int row = blockIdx.x * 4 + (tid >> 6);
    int c = tid & 63;
    int idx = g_idx[row];
    reinterpret_cast<float4*>(out)[(size_t)row * 64 + c] =
        reinterpret_cast<const float4*>(cb)[(size_t)idx * 64 + c];
}

extern "C" void kernel_launch(void* const* d_in, const int* in_sizes, int n_in,
                              void* d_out, int out_size) {
    const float* x  = (const float*)d_in[0];   // z_e_x  [8,4096,256] f32
    const float* cb = (const float*)d_in[1];   // codebook [8192,256] f32
    float* out = (float*)d_out;                // codes | idx | distances (f32)

    cudaFuncSetAttribute(vq_hmma_kernel,
                         cudaFuncAttributeMaxDynamicSharedMemorySize, SMEM_TOTAL);

    init_kernel<<<RTOT / 256, 256>>>();
    rowsq_kernel<<<(RTOT * 32) / 256, 256>>>(x, RTOT, 0);
    rowsq_kernel<<<(KTOT * 32) / 256, 256>>>(cb, KTOT, 1);
    prep_a_kernel<<<(RTOT * 64) / 256, 256>>>(x);
    prep_b_kernel<<<(KTOT * 64) / 256, 256>>>(cb);
    vq_hmma_kernel<<<NCTA, THREADS, SMEM_TOTAL>>>();
    final_kernel<<<RTOT / 256, 256>>>(out);
    fixup_kernel<<<64, 256>>>(x, cb, out);
    gather_kernel<<<RTOT / 4, 256>>>(cb, out);
}

// round 5
// speedup vs baseline: 2.6478x; 1.2367x over previous
#include <cuda_runtime.h>
#include <cuda_fp16.h>
#include <cstdint>

// ===== problem constants =====
#define RTOT  32768
#define CDIM  256
#define KTOT  8192
#define MT    128
#define NT    128
#define KSTEPS 16              // single product: hi*hi
#define NUM_MT (RTOT/MT)       // 256
#define NUM_NT (KTOT/NT)       // 64
#define JOBS  (NUM_MT*NUM_NT)  // 16384
#define NCTA  296              // 2 CTAs/SM persistent
#define THREADS 256

#define SMEM_A    0
#define SMEM_B    65536
#define SMEM_TOTAL 81920       // 64KB A + 16KB B ring

#define IDX_OFF  8388608
#define DIST_OFF (8388608+32768)

#define MARGIN 0.22f
#define FIXROWS 16

// ===== device globals (static scratch) =====
__device__ uint4 g_Aimg[(size_t)NUM_MT*4096];   // 16MB: [mtile][panel(16)][256 units] swizzled hi-fp16
__device__ uint4 g_Bimg[(size_t)NUM_NT*4096];   // 4MB
__device__ float g_cbsq[KTOT];
__device__ float g_xsq[RTOT];
__device__ int   g_idx[RTOT];
__device__ unsigned long long g_best[RTOT];
__device__ unsigned int g_best2[RTOT];
__device__ int g_fixcnt;
__device__ int g_fixrows[RTOT];

// ===== helpers =====
__device__ __forceinline__ uint32_t smem_u32(const void* p) {
    uint32_t a;
    asm("{ .reg .u64 t; cvta.to.shared.u64 t, %1; cvt.u32.u64 %0, t; }" : "=r"(a) : "l"(p));
    return a;
}
__device__ __forceinline__ void cp_async16(uint32_t sa, const void* g) {
    asm volatile("cp.async.cg.shared.global [%0], [%1], 16;" :: "r"(sa), "l"(g));
}
#define CP_COMMIT() asm volatile("cp.async.commit_group;" ::: "memory")
#define CP_WAIT(N)  asm volatile("cp.async.wait_group %0;" :: "n"(N) : "memory")

__device__ __forceinline__ void ldsm4(uint32_t* r, uint32_t addr) {
    asm volatile("ldmatrix.sync.aligned.m8n8.x4.shared.b16 {%0,%1,%2,%3}, [%4];"
        : "=r"(r[0]), "=r"(r[1]), "=r"(r[2]), "=r"(r[3]) : "r"(addr));
}
__device__ __forceinline__ void mma16816(float* c, const uint32_t* a, uint32_t b0, uint32_t b1) {
    asm volatile("mma.sync.aligned.m16n8k16.row.col.f32.f16.f16.f32 "
        "{%0,%1,%2,%3}, {%4,%5,%6,%7}, {%8,%9}, {%0,%1,%2,%3};"
        : "+f"(c[0]), "+f"(c[1]), "+f"(c[2]), "+f"(c[3])
        : "r"(a[0]), "r"(a[1]), "r"(a[2]), "r"(a[3]), "r"(b0), "r"(b1));
}
__device__ __forceinline__ uint32_t encf(float f) {
    uint32_t u = __float_as_uint(f);
    return (u & 0x80000000u) ? ~u : (u | 0x80000000u);
}
__device__ __forceinline__ float decf(uint32_t e) {
    uint32_t u = (e & 0x80000000u) ? (e & 0x7fffffffu) : ~e;
    return __uint_as_float(u);
}
__device__ __forceinline__ uint32_t packh2(__half a, __half b) {
    __half2 h = __halves2half2(a, b);
    return *reinterpret_cast<uint32_t*>(&h);
}

// ===== small kernels =====
__global__ void init_kernel() {
    int i = blockIdx.x * 256 + threadIdx.x;
    g_best[i] = ~0ull;
    g_best2[i] = 0xFFFFFFFFu;
    if (i == 0) g_fixcnt = 0;
}

__global__ void rowsq_kernel(const float* __restrict__ in, int rows, int which) {
    int gw = (blockIdx.x * blockDim.x + threadIdx.x) >> 5;
    int lane = threadIdx.x & 31;
    if (gw >= rows) return;
    const float4* p = reinterpret_cast<const float4*>(in) + (size_t)gw * (CDIM / 4);
    float s = 0.f;
#pragma unroll
    for (int k = 0; k < 2; ++k) {
        float4 v = p[lane + 32 * k];
        s += v.x*v.x + v.y*v.y + v.z*v.z + v.w*v.w;
    }
#pragma unroll
    for (int o = 16; o; o >>= 1) s += __shfl_xor_sync(0xffffffffu, s, o);
    if (lane == 0) { if (which == 0) g_xsq[gw] = s; else g_cbsq[gw] = s; }
}

// hi-fp16 pre-swizzled image: 16 panels of [tile-row 128 x k16]
__device__ __forceinline__ void prep_unit(const float* __restrict__ src, int t, uint4* img) {
    int row = t >> 5, u = t & 31;
    int ks = u >> 1, kh = u & 1;
    int kext = ks * 16 + kh * 8;
    const float* r = src + (size_t)row * CDIM;
    __half h[8];
#pragma unroll
    for (int i = 0; i < 8; ++i) h[i] = __float2half(r[kext + i]);
    uint4 val;
    val.x = packh2(h[0], h[1]); val.y = packh2(h[2], h[3]);
    val.z = packh2(h[4], h[5]); val.w = packh2(h[6], h[7]);
    int tile = row >> 7, rl = row & 127;
    int phys = (rl * 2 + kh) ^ ((rl >> 2) & 1);
    img[(size_t)tile * 4096 + ks * 256 + phys] = val;
}

__global__ void prep_a_kernel(const float* __restrict__ x) {
    prep_unit(x, blockIdx.x * 256 + threadIdx.x, g_Aimg);
}
__global__ void prep_b_kernel(const float* __restrict__ cb) {
    prep_unit(cb, blockIdx.x * 256 + threadIdx.x, g_Bimg);
}

// ===== main HMMA kernel =====
__device__ __forceinline__ void issue_B(uint32_t smemB, int slot, int nt, int panel, int tid) {
    const uint4* src = g_Bimg + (size_t)nt * 4096 + panel * 256 + tid;
    cp_async16(smemB + slot * 4096 + tid * 16, src);
}
__device__ __forceinline__ void issue_A(uint32_t smemA, int m, int tid) {
    const uint4* src = g_Aimg + (size_t)m * 4096 + tid;
#pragma unroll
    for (int i = 0; i < 16; ++i)
        cp_async16(smemA + (tid + i * 256) * 16, src + i * 256);
}
__device__ __forceinline__ void upd(float v, int c, float& bv, int& bi, float& sv) {
    if (v < bv) { sv = bv; bv = v; bi = c; }
    else if (v < sv) sv = v;
}

__global__ __launch_bounds__(THREADS, 2)
void vq_hmma_kernel() {
    extern __shared__ char smem[];
    uint32_t sb = smem_u32(smem);
    uint32_t smA = sb + SMEM_A, smB = sb + SMEM_B;

    int tid = threadIdx.x;
    int l = tid & 31, w = tid >> 5;
    int wm = w >> 1, wn = w & 1;

    // per-thread ldmatrix offsets (bytes inside a 4KB panel)
    uint32_t aoff[2], boff[4];
#pragma unroll
    for (int mt = 0; mt < 2; ++mt) {
        int row = wm * 32 + mt * 16 + (l & 15);
        int kh = l >> 4;
        aoff[mt] = (uint32_t)(((row * 2 + kh) ^ ((row >> 2) & 1)) << 4);
    }
#pragma unroll
    for (int nt4 = 0; nt4 < 4; ++nt4) {
        int code = wn * 64 + nt4 * 16 + (l & 7) + ((l >> 4) << 3);
        int kh = (l >> 3) & 1;
        boff[nt4] = (uint32_t)(((code * 2 + kh) ^ ((code >> 2) & 1)) << 4);
    }

    int start = (int)(((long long)blockIdx.x * JOBS) / NCTA);
    int end   = (int)(((long long)(blockIdx.x + 1) * JOBS) / NCTA);

    int cur_m = start >> 6;
    issue_A(smA, cur_m, tid); CP_COMMIT();
    {   int nt0 = start & 63;
        issue_B(smB, 0, nt0, 0, tid); CP_COMMIT();
        issue_B(smB, 1, nt0, 1, tid); CP_COMMIT();
        issue_B(smB, 2, nt0, 2, tid); CP_COMMIT();
    }

    // running per-row argmin state: rows indexed [mt][half]
    float rb[2][2] = {{3.4e38f,3.4e38f},{3.4e38f,3.4e38f}};
    float rs[2][2] = {{3.4e38f,3.4e38f},{3.4e38f,3.4e38f}};
    int   ri[2][2] = {{0,0},{0,0}};

    for (int j = start; j < end; ++j) {
        int ntj = j & 63;
        int jn = j + 1;
        bool nx_same = (jn < end) && ((jn >> 6) == cur_m);
        int nx_nt = jn & 63;

        float acc[2][8][4];
#pragma unroll
        for (int mt = 0; mt < 2; ++mt)
#pragma unroll
            for (int nb = 0; nb < 8; ++nb)
#pragma unroll
                for (int q = 0; q < 4; ++q) acc[mt][nb][q] = 0.f;

#pragma unroll 4
        for (int ks = 0; ks < KSTEPS; ++ks) {
            CP_WAIT(2);
            __syncthreads();
            int s = ks + 3;
            if (s < KSTEPS) issue_B(smB, s & 3, ntj, s, tid);
            else if (nx_same) issue_B(smB, s & 3, nx_nt, s - KSTEPS, tid);
            CP_COMMIT();

            uint32_t Apan = smA + ks * 4096;
            uint32_t Bpan = smB + (ks & 3) * 4096;
            uint32_t af[2][4], bf[4][4];
            ldsm4(af[0], Apan + aoff[0]);
            ldsm4(af[1], Apan + aoff[1]);
#pragma unroll
            for (int nt4 = 0; nt4 < 4; ++nt4) ldsm4(bf[nt4], Bpan + boff[nt4]);
#pragma unroll
            for (int mt = 0; mt < 2; ++mt)
#pragma unroll
                for (int nt4 = 0; nt4 < 4; ++nt4) {
                    mma16816(acc[mt][nt4*2  ], af[mt], bf[nt4][0], bf[nt4][1]);
                    mma16816(acc[mt][nt4*2+1], af[mt], bf[nt4][2], bf[nt4][3]);
                }
        }
        __syncthreads();   // all warps done with ring slots / A panels

        bool m_change = (jn < end) && !nx_same;
        if (m_change) {
            issue_A(smA, jn >> 6, tid); CP_COMMIT();
            issue_B(smB, 0, nx_nt, 0, tid); CP_COMMIT();
            issue_B(smB, 1, nx_nt, 1, tid); CP_COMMIT();
            issue_B(smB, 2, nx_nt, 2, tid); CP_COMMIT();
        }

        // ---- epilogue: val = |c|^2 - 2*dot ; running (best, idx, second) ----
        int nbase = ntj * 128 + wn * 64;
#pragma unroll
        for (int nb = 0; nb < 8; ++nb) {
            int c0 = nbase + nb * 8 + (l & 3) * 2;
            float q0 = __ldg(&g_cbsq[c0]);
            float q1 = __ldg(&g_cbsq[c0 + 1]);
#pragma unroll
            for (int mt = 0; mt < 2; ++mt) {
                upd(fmaf(-2.f, acc[mt][nb][0], q0), c0,     rb[mt][0], ri[mt][0], rs[mt][0]);
                upd(fmaf(-2.f, acc[mt][nb][1], q1), c0 + 1, rb[mt][0], ri[mt][0], rs[mt][0]);
                upd(fmaf(-2.f, acc[mt][nb][2], q0), c0,     rb[mt][1], ri[mt][1], rs[mt][1]);
                upd(fmaf(-2.f, acc[mt][nb][3], q1), c0 + 1, rb[mt][1], ri[mt][1], rs[mt][1]);
            }
        }

        if (m_change || jn == end) {
            // flush 4 rows: quad-merge then atomic dance
#pragma unroll
            for (int mt = 0; mt < 2; ++mt)
#pragma unroll
                for (int h = 0; h < 2; ++h) {
                    float bv = rb[mt][h], sv = rs[mt][h];
                    int bi = ri[mt][h];
#pragma unroll
                    for (int o = 1; o < 4; o <<= 1) {
                        float ov = __shfl_xor_sync(0xffffffffu, bv, o);
                        int   oi = __shfl_xor_sync(0xffffffffu, bi, o);
                        float os = __shfl_xor_sync(0xffffffffu, sv, o);
                        if (ov < bv || (ov == bv && oi < bi)) {
                            sv = fminf(bv, os); bv = ov; bi = oi;
                        } else {
                            sv = fminf(sv, ov);
                        }
                    }
                    if ((l & 3) == 0) {
                        int r = cur_m * MT + wm * 32 + mt * 16 + h * 8 + (l >> 2);
                        unsigned long long key =
                            ((unsigned long long)encf(bv) << 32) | (uint32_t)bi;
                        unsigned long long old = atomicMin(&g_best[r], key);
                        uint32_t oldenc = (uint32_t)(old >> 32);
                        uint32_t be = encf(bv);
                        uint32_t cand = min(encf(sv), max(be, oldenc));
                        atomicMin(&g_best2[r], cand);
                    }
                    rb[mt][h] = 3.4e38f; rs[mt][h] = 3.4e38f; ri[mt][h] = 0;
                }
            if (jn < end) cur_m = jn >> 6;
        }
    }
}

// ===== finalize: decode, flag rows with small approx gap =====
__global__ void final_kernel(float* __restrict__ out) {
    int i = blockIdx.x * 256 + threadIdx.x;
    unsigned long long key = g_best[i];
    int idx = (int)(uint32_t)key;
    float val = decf((uint32_t)(key >> 32));
    float sec = decf(g_best2[i]);
    out[IDX_OFF + i]  = (float)idx;
    out[DIST_OFF + i] = g_xsq[i] + val;
    g_idx[i] = idx;
    if (sec - val < MARGIN) {
        int p = atomicAdd(&g_fixcnt, 1);
        g_fixrows[p] = i;
    }
}

// ===== exact fp32 rescan for flagged rows: 16 rows/block, 4x4 reg tiles =====
__global__ __launch_bounds__(256) void fixup_kernel(const float* __restrict__ x,
                                                    const float* __restrict__ cb,
                                                    float* __restrict__ out) {
    __shared__ float4 xs[FIXROWS][64];
    __shared__ unsigned long long wk[FIXROWS][2];
    int tid = threadIdx.x;
    int n = g_fixcnt;
    int ngroups = (n + FIXROWS - 1) / FIXROWS;
    const float4* c4 = reinterpret_cast<const float4*>(cb);
    for (int g = blockIdx.x; g < ngroups; g += gridDim.x) {
        __syncthreads();
        for (int i = tid; i < FIXROWS * 64; i += 256) {
            int r = i >> 6, q = i & 63;
            int fr = g * FIXROWS + r;
            int row = g_fixrows[(fr < n) ? fr : g * FIXROWS];
            xs[r][q] = reinterpret_cast<const float4*>(x)[(size_t)row * 64 + q];
        }
        __syncthreads();
        int rg = tid >> 6;            // 4 row-groups of 4 rows
        int cg = tid & 63;
        float bv[4] = {3.4e38f,3.4e38f,3.4e38f,3.4e38f};
        int   bi[4] = {0,0,0,0};
        for (int k = 0; k < 32; ++k) {
            int c0 = k * 256 + cg * 4;
            float acc[4][4];
#pragma unroll
            for (int r = 0; r < 4; ++r)
#pragma unroll
                for (int cc = 0; cc < 4; ++cc) acc[r][cc] = 0.f;
#pragma unroll 8
            for (int q = 0; q < 64; ++q) {
                float4 xv[4];
#pragma unroll
                for (int r = 0; r < 4; ++r) xv[r] = xs[rg * 4 + r][q];
#pragma unroll
                for (int cc = 0; cc < 4; ++cc) {
                    float4 v = c4[(size_t)(c0 + cc) * 64 + q];
#pragma unroll
                    for (int r = 0; r < 4; ++r) {
                        acc[r][cc] = fmaf(v.x, xv[r].x, acc[r][cc]);
                        acc[r][cc] = fmaf(v.y, xv[r].y, acc[r][cc]);
                        acc[r][cc] = fmaf(v.z, xv[r].z, acc[r][cc]);
                        acc[r][cc] = fmaf(v.w, xv[r].w, acc[r][cc]);
                    }
                }
            }
#pragma unroll
            for (int cc = 0; cc < 4; ++cc) {
                float cq = __ldg(&g_cbsq[c0 + cc]);
#pragma unroll
                for (int r = 0; r < 4; ++r) {
                    float val = fmaf(-2.f, acc[r][cc], cq);
                    if (val < bv[r] || (val == bv[r] && c0 + cc < bi[r])) {
                        bv[r] = val; bi[r] = c0 + cc;
                    }
                }
            }
        }
        // reduce: warp shfl-min on packed keys, 2 warps per row-group
#pragma unroll
        for (int r = 0; r < 4; ++r) {
            unsigned long long key =
                ((unsigned long long)encf(bv[r]) << 32) | (uint32_t)bi[r];
#pragma unroll
            for (int o = 16; o; o >>= 1) {
                unsigned long long ok = __shfl_xor_sync(0xffffffffu, key, o);
                key = min(key, ok);
            }
            if ((tid & 31) == 0) wk[rg * 4 + r][(tid >> 5) & 1] = key;
        }
        __syncthreads();
        if (tid < FIXROWS) {
            int fr = g * FIXROWS + tid;
            if (fr < n) {
                unsigned long long best = min(wk[tid][0], wk[tid][1]);
                int row = g_fixrows[fr];
                int idx = (int)(uint32_t)best;
                out[IDX_OFF + row]  = (float)idx;
                out[DIST_OFF + row] = g_xsq[row] + decf((uint32_t)(best >> 32));
                g_idx[row] = idx;
            }
        }
    }
}

// ===== gather codes =====
__global__ void gather_kernel(const float* __restrict__ cb, float* __restrict__ out) {
    int tid = threadIdx.x;
    int row = blockIdx.x * 4 + (tid >> 6);
    int c = tid & 63;
    int idx = g_idx[row];
    reinterpret_cast<float4*>(out)[(size_t)row * 64 + c] =
        reinterpret_cast<const float4*>(cb)[(size_t)idx * 64 + c];
}

extern "C" void kernel_launch(void* const* d_in, const int* in_sizes, int n_in,
                              void* d_out, int out_size) {
    const float* x  = (const float*)d_in[0];   // z_e_x  [8,4096,256] f32
    const float* cb = (const float*)d_in[1];   // codebook [8192,256] f32
    float* out = (float*)d_out;                // codes | idx | distances (f32)

    cudaFuncSetAttribute(vq_hmma_kernel,
                         cudaFuncAttributeMaxDynamicSharedMemorySize, SMEM_TOTAL);

    init_kernel<<<RTOT / 256, 256>>>();
    rowsq_kernel<<<(RTOT * 32) / 256, 256>>>(x, RTOT, 0);
    rowsq_kernel<<<(KTOT * 32) / 256, 256>>>(cb, KTOT, 1);
    prep_a_kernel<<<(RTOT * 32) / 256, 256>>>(x);
    prep_b_kernel<<<(KTOT * 32) / 256, 256>>>(cb);
    vq_hmma_kernel<<<NCTA, THREADS, SMEM_TOTAL>>>();
    final_kernel<<<RTOT / 256, 256>>>(out);
    fixup_kernel<<<NCTA, 256>>>(x, cb, out);
    gather_kernel<<<RTOT / 4, 256>>>(cb, out);
}

// round 6
// speedup vs baseline: 2.7378x; 1.0340x over previous
#include <cuda_runtime.h>
#include <cuda_fp16.h>
#include <cstdint>

// ===== problem constants =====
#define RTOT  32768
#define CDIM  256
#define KTOT  8192
#define MT    128
#define NT    128
#define KSTEPS 16              // single product: hi*hi
#define NUM_MT (RTOT/MT)       // 256
#define NUM_NT (KTOT/NT)       // 64
#define JOBS  (NUM_MT*NUM_NT)  // 16384
#define NCTA  148
#define THREADS 256

#define SMEM_A    0
#define SMEM_B0   65536
#define SMEM_B1   131072
#define SMEM_TOTAL 196608      // A 64KB + B double buffer 2x64KB

#define IDX_OFF  8388608
#define DIST_OFF (8388608+32768)

#define VOFF 1024.0f
#define MARGIN 0.16f
#define FIXROWS 16

// ===== device globals (static scratch) =====
__device__ uint4 g_Aimg[(size_t)NUM_MT*4096];   // 16MB: [mtile][panel(16)][256 units] swizzled hi-fp16
__device__ uint4 g_Bimg[(size_t)NUM_NT*4096];   // 4MB
__device__ float g_cbsq[KTOT];
__device__ float g_cbsqo[KTOT];                 // cbsq + VOFF
__device__ float g_xsq[RTOT];
__device__ int   g_idx[RTOT];
__device__ unsigned long long g_best[RTOT];
__device__ unsigned int g_best2[RTOT];
__device__ int g_fixcnt;
__device__ int g_fixrows[RTOT];

// ===== helpers =====
__device__ __forceinline__ uint32_t smem_u32(const void* p) {
    uint32_t a;
    asm("{ .reg .u64 t; cvta.to.shared.u64 t, %1; cvt.u32.u64 %0, t; }" : "=r"(a) : "l"(p));
    return a;
}
__device__ __forceinline__ void cp_async16(uint32_t sa, const void* g) {
    asm volatile("cp.async.cg.shared.global [%0], [%1], 16;" :: "r"(sa), "l"(g));
}
#define CP_COMMIT() asm volatile("cp.async.commit_group;" ::: "memory")
#define CP_WAIT(N)  asm volatile("cp.async.wait_group %0;" :: "n"(N) : "memory")

__device__ __forceinline__ void ldsm4(uint32_t* r, uint32_t addr) {
    asm volatile("ldmatrix.sync.aligned.m8n8.x4.shared.b16 {%0,%1,%2,%3}, [%4];"
        : "=r"(r[0]), "=r"(r[1]), "=r"(r[2]), "=r"(r[3]) : "r"(addr));
}
__device__ __forceinline__ void mma16816(float* c, const uint32_t* a, uint32_t b0, uint32_t b1) {
    asm volatile("mma.sync.aligned.m16n8k16.row.col.f32.f16.f16.f32 "
        "{%0,%1,%2,%3}, {%4,%5,%6,%7}, {%8,%9}, {%0,%1,%2,%3};"
        : "+f"(c[0]), "+f"(c[1]), "+f"(c[2]), "+f"(c[3])
        : "r"(a[0]), "r"(a[1]), "r"(a[2]), "r"(a[3]), "r"(b0), "r"(b1));
}
__device__ __forceinline__ uint32_t encf(float f) {
    uint32_t u = __float_as_uint(f);
    return (u & 0x80000000u) ? ~u : (u | 0x80000000u);
}
__device__ __forceinline__ float decf(uint32_t e) {
    uint32_t u = (e & 0x80000000u) ? (e & 0x7fffffffu) : ~e;
    return __uint_as_float(u);
}
__device__ __forceinline__ uint32_t packh2(__half a, __half b) {
    __half2 h = __halves2half2(a, b);
    return *reinterpret_cast<uint32_t*>(&h);
}

// ===== small kernels =====
__global__ void init_kernel() {
    int i = blockIdx.x * 256 + threadIdx.x;
    g_best[i] = ~0ull;
    g_best2[i] = 0xFFFFFFFFu;
    if (i == 0) g_fixcnt = 0;
}

__global__ void rowsq_kernel(const float* __restrict__ in, int rows, int which) {
    int gw = (blockIdx.x * blockDim.x + threadIdx.x) >> 5;
    int lane = threadIdx.x & 31;
    if (gw >= rows) return;
    const float4* p = reinterpret_cast<const float4*>(in) + (size_t)gw * (CDIM / 4);
    float s = 0.f;
#pragma unroll
    for (int k = 0; k < 2; ++k) {
        float4 v = p[lane + 32 * k];
        s += v.x*v.x + v.y*v.y + v.z*v.z + v.w*v.w;
    }
#pragma unroll
    for (int o = 16; o; o >>= 1) s += __shfl_xor_sync(0xffffffffu, s, o);
    if (lane == 0) {
        if (which == 0) g_xsq[gw] = s;
        else { g_cbsq[gw] = s; g_cbsqo[gw] = s + VOFF; }
    }
}

// hi-fp16 pre-swizzled image: 16 panels of [tile-row 128 x k16]
__device__ __forceinline__ void prep_unit(const float* __restrict__ src, int t, uint4* img) {
    int row = t >> 5, u = t & 31;
    int ks = u >> 1, kh = u & 1;
    int kext = ks * 16 + kh * 8;
    const float* r = src + (size_t)row * CDIM;
    __half h[8];
#pragma unroll
    for (int i = 0; i < 8; ++i) h[i] = __float2half(r[kext + i]);
    uint4 val;
    val.x = packh2(h[0], h[1]); val.y = packh2(h[2], h[3]);
    val.z = packh2(h[4], h[5]); val.w = packh2(h[6], h[7]);
    int tile = row >> 7, rl = row & 127;
    int phys = (rl * 2 + kh) ^ ((rl >> 2) & 1);
    img[(size_t)tile * 4096 + ks * 256 + phys] = val;
}

__global__ void prep_a_kernel(const float* __restrict__ x) {
    prep_unit(x, blockIdx.x * 256 + threadIdx.x, g_Aimg);
}
__global__ void prep_b_kernel(const float* __restrict__ cb) {
    prep_unit(cb, blockIdx.x * 256 + threadIdx.x, g_Bimg);
}

// ===== main HMMA kernel =====
__device__ __forceinline__ void issue_Bjob(uint32_t smemB, int nt, int tid) {
    const uint4* src = g_Bimg + (size_t)nt * 4096 + tid;
#pragma unroll
    for (int i = 0; i < 16; ++i)
        cp_async16(smemB + (tid + i * 256) * 16, src + i * 256);
}
__device__ __forceinline__ void issue_A(uint32_t smemA, int m, int tid) {
    const uint4* src = g_Aimg + (size_t)m * 4096 + tid;
#pragma unroll
    for (int i = 0; i < 16; ++i)
        cp_async16(smemA + (tid + i * 256) * 16, src + i * 256);
}

__global__ __launch_bounds__(THREADS, 1)
void vq_hmma_kernel() {
    extern __shared__ char smem[];
    uint32_t sb = smem_u32(smem);
    uint32_t smA = sb + SMEM_A;
    uint32_t smB[2] = { sb + SMEM_B0, sb + SMEM_B1 };

    int tid = threadIdx.x;
    int l = tid & 31, w = tid >> 5;
    int wm = w >> 1, wn = w & 1;

    // per-thread ldmatrix offsets (bytes inside a 4KB panel)
    uint32_t aoff[2], boff[4];
#pragma unroll
    for (int mt = 0; mt < 2; ++mt) {
        int row = wm * 32 + mt * 16 + (l & 15);
        int kh = l >> 4;
        aoff[mt] = (uint32_t)(((row * 2 + kh) ^ ((row >> 2) & 1)) << 4);
    }
#pragma unroll
    for (int nt4 = 0; nt4 < 4; ++nt4) {
        int code = wn * 64 + nt4 * 16 + (l & 7) + ((l >> 4) << 3);
        int kh = (l >> 3) & 1;
        boff[nt4] = (uint32_t)(((code * 2 + kh) ^ ((code >> 2) & 1)) << 4);
    }

    int start = (int)(((long long)blockIdx.x * JOBS) / NCTA);
    int end   = (int)(((long long)(blockIdx.x + 1) * JOBS) / NCTA);

    int cur_m = start >> 6;
    issue_A(smA, cur_m, tid); CP_COMMIT();
    issue_Bjob(smB[0], start & 63, tid); CP_COMMIT();
    CP_WAIT(0);
    __syncthreads();
    int buf = 0;

    // running per-row argmin state: rows indexed [mt][half]; values offset by VOFF
    float rb[2][2] = {{3.4e38f,3.4e38f},{3.4e38f,3.4e38f}};
    float rs[2][2] = {{3.4e38f,3.4e38f},{3.4e38f,3.4e38f}};
    int   ri[2][2] = {{0,0},{0,0}};

    int cbase = (start & 63) * 0;  // placeholder, computed per job
    (void)cbase;

    for (int j = start; j < end; ++j) {
        int ntj = j & 63;
        int jn = j + 1;
        bool nx_same = (jn < end) && ((jn >> 6) == cur_m);

        // prefetch next job's B into the other buffer (overlaps full job)
        if (nx_same) { issue_Bjob(smB[buf ^ 1], jn & 63, tid); CP_COMMIT(); }

        // prefetch offset |c|^2 for this thread's 16 columns
        float qv[16];
        int qbase = ntj * 128 + wn * 64 + (l & 3) * 2;
#pragma unroll
        for (int nb = 0; nb < 8; ++nb) {
            qv[nb * 2]     = __ldg(&g_cbsqo[qbase + nb * 8]);
            qv[nb * 2 + 1] = __ldg(&g_cbsqo[qbase + nb * 8 + 1]);
        }

        float acc[2][8][4];
#pragma unroll
        for (int mt = 0; mt < 2; ++mt)
#pragma unroll
            for (int nb = 0; nb < 8; ++nb)
#pragma unroll
                for (int q = 0; q < 4; ++q) acc[mt][nb][q] = 0.f;

        uint32_t Bbase = smB[buf];
#pragma unroll
        for (int ks = 0; ks < KSTEPS; ++ks) {
            uint32_t Apan = smA + ks * 4096;
            uint32_t Bpan = Bbase + ks * 4096;
            uint32_t af[2][4], bf[4][4];
            ldsm4(af[0], Apan + aoff[0]);
            ldsm4(af[1], Apan + aoff[1]);
#pragma unroll
            for (int nt4 = 0; nt4 < 4; ++nt4) ldsm4(bf[nt4], Bpan + boff[nt4]);
#pragma unroll
            for (int mt = 0; mt < 2; ++mt)
#pragma unroll
                for (int nt4 = 0; nt4 < 4; ++nt4) {
                    mma16816(acc[mt][nt4*2  ], af[mt], bf[nt4][0], bf[nt4][1]);
                    mma16816(acc[mt][nt4*2+1], af[mt], bf[nt4][2], bf[nt4][3]);
                }
        }

        // ---- epilogue: packed-key min + exact second, branchless ----
#pragma unroll
        for (int mt = 0; mt < 2; ++mt)
#pragma unroll
            for (int h = 0; h < 2; ++h) {
                uint32_t k1 = 0xFFFFFFFFu, k2 = 0xFFFFFFFFu;
#pragma unroll
                for (int nb = 0; nb < 8; ++nb)
#pragma unroll
                    for (int c = 0; c < 2; ++c) {
                        float v = fmaf(-2.f, acc[mt][nb][h * 2 + c], qv[nb * 2 + c]);
                        uint32_t k = (__float_as_uint(v) & 0xFFFFFFF0u) | (uint32_t)(nb * 2 + c);
                        uint32_t t = max(k1, k);
                        k1 = min(k1, k);
                        k2 = min(k2, t);
                    }
                float v1 = __uint_as_float(k1 & 0xFFFFFFF0u);
                float v2 = __uint_as_float(k2 & 0xFFFFFFF0u);
                int li = (int)(k1 & 15u);
                int gidx = qbase + (li >> 1) * 8 + (li & 1);
                if (v1 < rb[mt][h]) {
                    rs[mt][h] = fminf(rb[mt][h], v2);
                    rb[mt][h] = v1; ri[mt][h] = gidx;
                } else {
                    rs[mt][h] = fminf(rs[mt][h], v1);
                }
            }

        bool m_change = (jn < end) && !nx_same;
        if (m_change || jn == end) {
            // flush 4 rows: quad-merge then atomic dance
#pragma unroll
            for (int mt = 0; mt < 2; ++mt)
#pragma unroll
                for (int h = 0; h < 2; ++h) {
                    float bv = rb[mt][h], sv = rs[mt][h];
                    int bi = ri[mt][h];
#pragma unroll
                    for (int o = 1; o < 4; o <<= 1) {
                        float ov = __shfl_xor_sync(0xffffffffu, bv, o);
                        int   oi = __shfl_xor_sync(0xffffffffu, bi, o);
                        float os = __shfl_xor_sync(0xffffffffu, sv, o);
                        if (ov < bv || (ov == bv && oi < bi)) {
                            sv = fminf(bv, os); bv = ov; bi = oi;
                        } else {
                            sv = fminf(sv, ov);
                        }
                    }
                    if ((l & 3) == 0) {
                        int r = cur_m * MT + wm * 32 + mt * 16 + h * 8 + (l >> 2);
                        unsigned long long key =
                            ((unsigned long long)encf(bv) << 32) | (uint32_t)bi;
                        unsigned long long old = atomicMin(&g_best[r], key);
                        uint32_t oldenc = (uint32_t)(old >> 32);
                        uint32_t be = encf(bv);
                        uint32_t cand = min(encf(sv), max(be, oldenc));
                        atomicMin(&g_best2[r], cand);
                    }
                    rb[mt][h] = 3.4e38f; rs[mt][h] = 3.4e38f; ri[mt][h] = 0;
                }
        }

        if (nx_same) {
            CP_WAIT(0);
            __syncthreads();
            buf ^= 1;
        } else if (jn < end) {
            __syncthreads();          // all warps done reading A
            cur_m = jn >> 6;
            issue_A(smA, cur_m, tid); CP_COMMIT();
            issue_Bjob(smB[buf], jn & 63, tid); CP_COMMIT();
            CP_WAIT(0);
            __syncthreads();
        }
    }
}

// ===== finalize: decode, flag rows with small approx gap =====
__global__ void final_kernel(float* __restrict__ out) {
    int i = blockIdx.x * 256 + threadIdx.x;
    unsigned long long key = g_best[i];
    int idx = (int)(uint32_t)key;
    float val = decf((uint32_t)(key >> 32)) - VOFF;
    float sec = decf(g_best2[i]) - VOFF;
    out[IDX_OFF + i]  = (float)idx;
    out[DIST_OFF + i] = g_xsq[i] + val;
    g_idx[i] = idx;
    if (sec - val < MARGIN) {
        int p = atomicAdd(&g_fixcnt, 1);
        g_fixrows[p] = i;
    }
}

// ===== exact fp32 rescan for flagged rows: 16 rows/block, 4x4 reg tiles =====
__global__ __launch_bounds__(256) void fixup_kernel(const float* __restrict__ x,
                                                    const float* __restrict__ cb,
                                                    float* __restrict__ out) {
    __shared__ float4 xs[FIXROWS][64];
    __shared__ unsigned long long wk[FIXROWS][2];
    int tid = threadIdx.x;
    int n = g_fixcnt;
    int ngroups = (n + FIXROWS - 1) / FIXROWS;
    const float4* c4 = reinterpret_cast<const float4*>(cb);
    for (int g = blockIdx.x; g < ngroups; g += gridDim.x) {
        __syncthreads();
        for (int i = tid; i < FIXROWS * 64; i += 256) {
            int r = i >> 6, q = i & 63;
            int fr = g * FIXROWS + r;
            int row = g_fixrows[(fr < n) ? fr : g * FIXROWS];
            xs[r][q] = reinterpret_cast<const float4*>(x)[(size_t)row * 64 + q];
        }
        __syncthreads();
        int rg = tid >> 6;            // 4 row-groups of 4 rows
        int cg = tid & 63;
        float bv[4] = {3.4e38f,3.4e38f,3.4e38f,3.4e38f};
        int   bi[4] = {0,0,0,0};
        for (int k = 0; k < 32; ++k) {
            int c0 = k * 256 + cg * 4;
            float acc[4][4];
#pragma unroll
            for (int r = 0; r < 4; ++r)
#pragma unroll
                for (int cc = 0; cc < 4; ++cc) acc[r][cc] = 0.f;
#pragma unroll 8
            for (int q = 0; q < 64; ++q) {
                float4 xv[4];
#pragma unroll
                for (int r = 0; r < 4; ++r) xv[r] = xs[rg * 4 + r][q];
#pragma unroll
                for (int cc = 0; cc < 4; ++cc) {
                    float4 v = c4[(size_t)(c0 + cc) * 64 + q];
#pragma unroll
                    for (int r = 0; r < 4; ++r) {
                        acc[r][cc] = fmaf(v.x, xv[r].x, acc[r][cc]);
                        acc[r][cc] = fmaf(v.y, xv[r].y, acc[r][cc]);
                        acc[r][cc] = fmaf(v.z, xv[r].z, acc[r][cc]);
                        acc[r][cc] = fmaf(v.w, xv[r].w, acc[r][cc]);
                    }
                }
            }
#pragma unroll
            for (int cc = 0; cc < 4; ++cc) {
                float cq = __ldg(&g_cbsq[c0 + cc]);
#pragma unroll
                for (int r = 0; r < 4; ++r) {
                    float val = fmaf(-2.f, acc[r][cc], cq);
                    if (val < bv[r] || (val == bv[r] && c0 + cc < bi[r])) {
                        bv[r] = val; bi[r] = c0 + cc;
                    }
                }
            }
        }
        // reduce: warp shfl-min on packed keys, 2 warps per row-group
#pragma unroll
        for (int r = 0; r < 4; ++r) {
            unsigned long long key =
                ((unsigned long long)encf(bv[r]) << 32) | (uint32_t)bi[r];
#pragma unroll
            for (int o = 16; o; o >>= 1) {
                unsigned long long ok = __shfl_xor_sync(0xffffffffu, key, o);
                key = min(key, ok);
            }
            if ((tid & 31) == 0) wk[rg * 4 + r][(tid >> 5) & 1] = key;
        }
        __syncthreads();
        if (tid < FIXROWS) {
            int fr = g * FIXROWS + tid;
            if (fr < n) {
                unsigned long long best = min(wk[tid][0], wk[tid][1]);
                int row = g_fixrows[fr];
                int idx = (int)(uint32_t)best;
                out[IDX_OFF + row]  = (float)idx;
                out[DIST_OFF + row] = g_xsq[row] + decf((uint32_t)(best >> 32));
                g_idx[row] = idx;
            }
        }
    }
}

// ===== gather codes =====
__global__ void gather_kernel(const float* __restrict__ cb, float* __restrict__ out) {
    int tid = threadIdx.x;
    int row = blockIdx.x * 4 + (tid >> 6);
    int c = tid & 63;
    int idx = g_idx[row];
    reinterpret_cast<float4*>(out)[(size_t)row * 64 + c] =
        reinterpret_cast<const float4*>(cb)[(size_t)idx * 64 + c];
}

extern "C" void kernel_launch(void* const* d_in, const int* in_sizes, int n_in,
                              void* d_out, int out_size) {
    const float* x  = (const float*)d_in[0];   // z_e_x  [8,4096,256] f32
    const float* cb = (const float*)d_in[1];   // codebook [8192,256] f32
    float* out = (float*)d_out;                // codes | idx | distances (f32)

    cudaFuncSetAttribute(vq_hmma_kernel,
                         cudaFuncAttributeMaxDynamicSharedMemorySize, SMEM_TOTAL);

    init_kernel<<<RTOT / 256, 256>>>();
    rowsq_kernel<<<(RTOT * 32) / 256, 256>>>(x, RTOT, 0);
    rowsq_kernel<<<(KTOT * 32) / 256, 256>>>(cb, KTOT, 1);
    prep_a_kernel<<<(RTOT * 32) / 256, 256>>>(x);
    prep_b_kernel<<<(KTOT * 32) / 256, 256>>>(cb);
    vq_hmma_kernel<<<NCTA, THREADS, SMEM_TOTAL>>>();
    final_kernel<<<RTOT / 256, 256>>>(out);
    fixup_kernel<<<NCTA, 256>>>(x, cb, out);
    gather_kernel<<<RTOT / 4, 256>>>(cb, out);
}